// round 2
// baseline (speedup 1.0000x reference)
#include <cuda_runtime.h>

#define NL 51
#define LS 53
#define STARTI 51
#define ENDI 52
#define LOG2E 1.4426950408889634f
#define LN2   0.6931471805599453f

typedef unsigned long long ull;

__device__ __forceinline__ ull f2pack(float lo, float hi) {
    ull u;
    asm("mov.b64 %0, {%1, %2};" : "=l"(u) : "f"(lo), "f"(hi));
    return u;
}
__device__ __forceinline__ void f2fma(ull& d, ull a, ull b) {
    asm("fma.rn.f32x2 %0, %1, %2, %0;" : "+l"(d) : "l"(a), "l"(b));
}
__device__ __forceinline__ ull f2add(ull a, ull b) {
    ull d;
    asm("add.rn.f32x2 %0, %1, %2;" : "=l"(d) : "l"(a), "l"(b));
    return d;
}
__device__ __forceinline__ float2 f2unpack(ull u) {
    float lo, hi;
    asm("mov.b64 {%0, %1}, %2;" : "=f"(lo), "=f"(hi) : "l"(u));
    return make_float2(lo, hi);
}
__device__ __forceinline__ float ex2_approx(float x) {
    float r;
    asm("ex2.approx.f32 %0, %1;" : "=f"(r) : "f"(x));
    return r;
}
__device__ __forceinline__ float rcp_approx(float x) {
    float r;
    asm("rcp.approx.f32 %0, %1;" : "=f"(r) : "f"(x));
    return r;
}

// ---------------------------------------------------------------------------
// Gold score: out[b] = sum_unary + sum_binary  (fully parallel gather+reduce)
// ---------------------------------------------------------------------------
__global__ void crf_gold(const float* __restrict__ logits,
                         const int* __restrict__ labels,
                         const int* __restrict__ lens,
                         const float* __restrict__ T,
                         float* __restrict__ out, int S)
{
    __shared__ float sT[LS * LS];
    __shared__ float red[8];
    int b = blockIdx.x, tid = threadIdx.x;
    for (int i = tid; i < LS * LS; i += blockDim.x) sT[i] = T[i];
    __syncthreads();

    int len = lens[b];
    if (len < 1) len = 1;
    if (len > S) len = S;

    const int*   lab = labels + (size_t)b * S;
    const float* lg  = logits + (size_t)b * S * NL;

    float s = 0.f;
    // len+1 transitions (j = 0..len), len unary terms (j = 0..len-1)
    for (int j = tid; j <= len; j += 256) {
        int from = (j == 0)   ? STARTI : lab[j - 1];
        int to   = (j == len) ? ENDI   : lab[j];
        s += sT[to * LS + from];
        if (j < len) s += lg[(size_t)j * NL + to];
    }
    #pragma unroll
    for (int o = 16; o; o >>= 1) s += __shfl_xor_sync(0xffffffffu, s, o);
    if ((tid & 31) == 0) red[tid >> 5] = s;
    __syncthreads();
    if (tid == 0) {
        float v = 0.f;
        #pragma unroll
        for (int i = 0; i < 8; i++) v += red[i];
        out[b] = v;
    }
}

// ---------------------------------------------------------------------------
// Forward (norm) recursion in the exp domain, self-normalized by w[START].
// One CTA (64 threads = 2 warps) per batch element; thread = target state.
// Double-buffered shared state -> one __syncthreads per timestep.
// ---------------------------------------------------------------------------
__global__ void __launch_bounds__(64) crf_fwd(const float* __restrict__ logits,
                                              const int* __restrict__ lens,
                                              const float* __restrict__ T,
                                              float* __restrict__ out, int S)
{
    __shared__ __align__(16) float shw[2][64];
    __shared__ float sh_acc;

    int b = blockIdx.x, tid = threadIdx.x;
    int len = lens[b];
    if (len < 1) len = 1;
    if (len > S) len = S;

    const float* lg = logits + (size_t)b * S * NL;

    // Per-thread row of E = exp(T[to,:] - Tmax[to]), packed f32x2 pairs.
    ull   E[28];
    float Tmax = 0.f, TmaxL2 = 0.f, Gc = 0.f;
    if (tid < LS) {
        const float* row = T + tid * LS;
        float m = row[0];
        #pragma unroll
        for (int f = 1; f < LS; f++) m = fmaxf(m, row[f]);
        Tmax   = m;
        TmaxL2 = m * LOG2E;
        #pragma unroll
        for (int p = 0; p < 28; p++) {
            int f0 = 2 * p, f1 = f0 + 1;
            float a = (f0 < LS) ? __expf(row[f0] - m) : 0.f;
            float c = (f1 < LS) ? __expf(row[f1] - m) : 0.f;
            E[p] = f2pack(a, c);
        }
        Gc = __expf(Tmax - 100.0f);   // exp(logit_pad(-100) + Tmax) for START/END
    }

    // w0 = exp(alpha0 - alpha0[START]) : 1 at START, ~0 elsewhere
    shw[0][tid] = (tid == STARTI) ? 1.f : 0.f;
    shw[1][tid] = 0.f;

    float acc = 0.f;       // running sum of log2(Z_t)  (thread STARTI only)
    float g0 = 0.f, g1 = 0.f;   // 2-deep logit prefetch
    if (tid < NL) {
        g0 = lg[tid];
        if (len > 1) g1 = lg[NL + tid];
    }
    __syncthreads();

    for (int t = 0; t < len; t++) {
        const float* win  = shw[t & 1];
        float*       wout = shw[(t & 1) ^ 1];

        float w51 = win[STARTI];           // >= 1 by construction
        float r   = rcp_approx(w51);

        if (tid < LS) {
            float G = (tid < NL) ? ex2_approx(__fmaf_rn(g0, LOG2E, TmaxL2)) : Gc;

            ull a0 = 0, a1 = 0, a2 = 0, a3 = 0;
            const ulonglong2* wv = reinterpret_cast<const ulonglong2*>(win);
            #pragma unroll
            for (int q = 0; q < 14; q += 2) {
                ulonglong2 v0 = wv[q];
                ulonglong2 v1 = wv[q + 1];
                f2fma(a0, E[2 * q],     v0.x);
                f2fma(a1, E[2 * q + 1], v0.y);
                f2fma(a2, E[2 * q + 2], v1.x);
                f2fma(a3, E[2 * q + 3], v1.y);
            }
            float2 p = f2unpack(f2add(f2add(a0, a1), f2add(a2, a3)));
            float  s = p.x + p.y;

            float wn = G * s * r;
            wout[tid] = wn;
            if (tid == STARTI) acc += __log2f(wn);   // wn(START) = Z_t >= 1

            g0 = g1;
            g1 = ((t + 2) < len && tid < NL) ? lg[(size_t)(t + 2) * NL + tid] : 0.f;
        }
        __syncthreads();
    }

    if (tid == STARTI) sh_acc = acc;
    __syncthreads();

    if (tid == ENDI) {
        const float* wfin = shw[len & 1];
        ull a0 = 0, a1 = 0, a2 = 0, a3 = 0;
        const ulonglong2* wv = reinterpret_cast<const ulonglong2*>(wfin);
        #pragma unroll
        for (int q = 0; q < 14; q += 2) {
            ulonglong2 v0 = wv[q];
            ulonglong2 v1 = wv[q + 1];
            f2fma(a0, E[2 * q],     v0.x);
            f2fma(a1, E[2 * q + 1], v0.y);
            f2fma(a2, E[2 * q + 2], v1.x);
            f2fma(a3, E[2 * q + 3], v1.y);
        }
        float2 p   = f2unpack(f2add(f2add(a0, a1), f2add(a2, a3)));
        float  dot = p.x + p.y;
        // norm = alpha_L[START] + log( sum_f exp(T[END,f]-Tmax_END) * v_L[f] ) + Tmax_END
        float norm = sh_acc * LN2 + __logf(dot) - __logf(wfin[STARTI]) + Tmax;
        out[b] = out[b] - norm;   // gold (written by crf_gold) minus norm
    }
}

extern "C" void kernel_launch(void* const* d_in, const int* in_sizes, int n_in,
                              void* d_out, int out_size)
{
    const float* logits = (const float*)d_in[0];
    const int*   labels = (const int*)d_in[1];
    const int*   lens   = (const int*)d_in[2];
    const float* T      = (const float*)d_in[3];
    float*       out    = (float*)d_out;

    int B = out_size;                       // 256
    int S = in_sizes[1] / B;                // 2048 (labels is B*S)

    crf_gold<<<B, 256>>>(logits, labels, lens, T, out, S);
    crf_fwd <<<B, 64>>>(logits, lens, T, out, S);
}